// round 6
// baseline (speedup 1.0000x reference)
#include <cuda_runtime.h>

#define BB 32
#define NN 2048
#define EPSF 5e-4f
#define HH 5.0f          /* fixed Chebyshev domain half-width */
#define TPB 1024
#define NW 32            /* warps per block */

__device__ float g_rowSum[BB];
__device__ int   g_ctr;          // zero-init; self-resetting

// One block per row (grid=32, 1024 threads). All phases in-block:
//  1) load scores/labels, E=exp(s), pair-precompute (p=a+b, r2=2ab), histogram
//  2) node sums: lane k = Chebyshev-Gauss node, paired sigmoid: one RCP per 2 j
//  3) warp0: combine F + DCT-II coeffs; warp1: histogram -> rank boundaries
//  4) Clenshaw eval at 2 pts/thread + rank-based maxDCG, joint reduction
//  5) last block (global counter) computes the mean.
__global__ __launch_bounds__(TPB, 1)
void fused(const float* __restrict__ yp, const float* __restrict__ yt,
           float* __restrict__ out) {
    int b = blockIdx.x, t = threadIdx.x, w = t >> 5, lane = t & 31;
    __shared__ float2 sP[NN/2];                 // (p, r2) per j-pair
    __shared__ float sF[NW*33];                 // padded warp partials
    __shared__ float sCoef[32];
    __shared__ unsigned long long sHist[NW];
    __shared__ int sOff[4];
    __shared__ float sRed[2*NW];

    // ---- phase 1: loads, exp, pair precompute, packed histogram ----
    float2 sc = ((const float2*)(yp + b*NN))[t];    // scores 2t, 2t+1
    float2 lb = ((const float2*)(yt + b*NN))[t];
    int v0 = (int)lb.x, v1 = (int)lb.y;
    float ea = __expf(sc.x), eb = __expf(sc.y);
    sP[t] = make_float2(ea + eb, 2.f*ea*eb);
    unsigned long long pk = (1ULL << (12*v0)) + (1ULL << (12*v1));
    #pragma unroll
    for (int o = 16; o; o >>= 1) pk += __shfl_xor_sync(0xffffffffu, pk, o);
    if (lane == 0) sHist[w] = pk;

    // node weight: x_k = HH*cos(pi(2k+1)/64), W = e^{x_k}
    float W  = __expf(HH * cospif((float)(2*lane + 1) * (1.0f/64.0f)));
    float W2 = W * W;
    __syncthreads();

    // ---- phase 2: paired node sums. warp w owns pairs [32w, 32w+32) ----
    // sig(a)+sig(b) = (2ab + (a+b)W) / ((a+W)(b+W)), denom = W^2 + pW + ab
    float acc = 0.f;
    #pragma unroll
    for (int i = 0; i < 32; i++) {
        float2 pr = sP[w*32 + i];
        float h = fmaf(0.5f, pr.y, W2);          // W^2 + ab
        float d = fmaf(pr.x, W, h);              // denom
        float n = fmaf(pr.x, W, pr.y);           // numer
        acc = fmaf(n, __frcp_rn(d), acc);
    }
    sF[w*33 + lane] = acc;
    __syncthreads();

    // ---- phase 3: warp0 F-combine + DCT; warp1 histogram boundaries ----
    if (w == 0) {
        float F = 0.f;
        #pragma unroll
        for (int i = 0; i < NW; i++) F += sF[i*33 + lane];
        // DCT-II: c_m = (2/32) sum_k F_k cos(pi m(2k+1)/64); c_0 halved.
        float m = (float)lane;
        float c = 0.f;
        #pragma unroll
        for (int k = 0; k < 32; k++) {
            float fk = __shfl_sync(0xffffffffu, F, k);
            c = fmaf(fk, cospif(m * (float)(2*k + 1) * (1.0f/64.0f)), c);
        }
        c *= (2.0f/32.0f);
        if (lane == 0) c *= 0.5f;
        sCoef[lane] = c;
    } else if (w == 1) {
        unsigned long long hh = sHist[lane];
        #pragma unroll
        for (int o = 16; o; o >>= 1) hh += __shfl_xor_sync(0xffffffffu, hh, o);
        if (lane == 0) {
            int c4 = (int)((hh >> 48) & 0xFFF);
            int c3 = (int)((hh >> 36) & 0xFFF);
            int c2 = (int)((hh >> 24) & 0xFFF);
            int c1 = (int)((hh >> 12) & 0xFFF);
            sOff[0] = c4;                       // ranks [0,B4)      -> 4
            sOff[1] = c4 + c3;                  // [B4,B3)           -> 3
            sOff[2] = c4 + c3 + c2;             // [B3,B2)           -> 2
            sOff[3] = c4 + c3 + c2 + c1;        // [B2,B1)->1 else 0
        }
    }
    __syncthreads();

    // ---- phase 4: Clenshaw eval (2 points/thread) + rank-based maxDCG ----
    int B4 = sOff[0], B3 = sOff[1], B2 = sOff[2], B1 = sOff[3];
    float numer = 0.f, mdcg = 0.f;
    #pragma unroll
    for (int i = 0; i < 2; i++) {
        int n = 2*t + i;
        float s = i ? sc.y : sc.x;
        int v = i ? v1 : v0;
        float u = fminf(fmaxf(s * (1.0f/HH), -1.f), 1.f);
        float tu = u + u, y1 = 0.f, y2 = 0.f;
        #pragma unroll
        for (int m = 31; m >= 1; m--) {
            float tmp = fmaf(tu, y1, sCoef[m]) - y2;
            y2 = y1; y1 = tmp;
        }
        float F = fmaf(u, y1, sCoef[0]) - y2;             // interpolated F(s)
        float gain = (float)((1 << v) - 1);
        numer += __fdividef(gain, __log2f(1.5f + F));     // pos = 0.5 + F

        int vr = 4 - (n >= B4) - (n >= B3) - (n >= B2) - (n >= B1);
        float g2 = (float)((1 << vr) - 1);
        mdcg += __fdividef(g2, __log2f((float)(n + 2))); // rank r = n
    }
    #pragma unroll
    for (int o = 16; o; o >>= 1) {
        numer += __shfl_xor_sync(0xffffffffu, numer, o);
        mdcg  += __shfl_xor_sync(0xffffffffu, mdcg,  o);
    }
    if (lane == 0) { sRed[w] = numer; sRed[NW + w] = mdcg; }
    __syncthreads();

    if (t == 0) {
        float ns = 0.f, ds = 0.f;
        #pragma unroll
        for (int i = 0; i < NW; i++) { ns += sRed[i]; ds += sRed[NW + i]; }
        g_rowSum[b] = ns / fmaxf(ds, EPSF);
        __threadfence();
        int d = atomicAdd(&g_ctr, 1);
        if (d == BB - 1) {               // last row finisher -> mean
            g_ctr = 0;                   // self-reset for graph replay
            __threadfence();
            float sAll = 0.f;
            #pragma unroll
            for (int i = 0; i < BB; i++) sAll += g_rowSum[i];
            out[0] = sAll * (1.0f/BB);
        }
    }
}

extern "C" void kernel_launch(void* const* d_in, const int* in_sizes, int n_in,
                              void* d_out, int out_size) {
    const float* yp = (const float*)d_in[0];
    const float* yt = (const float*)d_in[1];
    float* out = (float*)d_out;
    (void)in_sizes; (void)n_in; (void)out_size;

    fused<<<BB, TPB>>>(yp, yt, out);
}